// round 7
// baseline (speedup 1.0000x reference)
#include <cuda_runtime.h>
#include <cuda_fp16.h>

// RoIAlign (torchvision aligned=True, sampling_ratio=2) — per-batch pipelined:
//   T_b: transpose x[b] [C,H,W] f32 -> g_xt[b] [H,W,C] f16
//   G_b: gather from g_xt[b] (warp = 1 output position, lanes span channels,
//        one LDG.128 per corner per lane), smem-staged coalesced output.
// Launch order T0,G0,T1,G1,... with PDL: G_b starts at T_b completion and
// fires its programmatic trigger at entry so T_{b+1} overlaps G_b.

#define B_    8
#define N_    64
#define C_    256
#define C2_   (C_ / 2)
#define H_    128
#define W_    128
#define HW_   (H_ * W_)
#define OUT_H 6
#define OUT_W 6
#define NPOS  36
#define PPB   6              // positions per gather block (one oh row)
#define WPB   6              // warps per gather block
#define TPB   (WPB * 32)     // 192 threads

// 8 * 16384 * 256 halves = 64 MB scratch (__device__ global: allowed)
__device__ __half g_xt[(size_t)B_ * HW_ * C_];

// ---------------------------------------------------------------------------
// Transpose one batch: [C, HW] f32 -> [HW, C] f16. Grid (512, 4).
// ---------------------------------------------------------------------------
__global__ void __launch_bounds__(256)
transpose_kernel(const float* __restrict__ x, int b)
{
    __shared__ float sm[64][33];

    const int c0 = blockIdx.y * 64;
    const int s0 = blockIdx.x * 32;
    const int tid = threadIdx.x;
    const int tx = tid & 31;
    const int ty = tid >> 5;

    const float* src = x + ((size_t)b * C_ + c0) * HW_ + s0;
    #pragma unroll
    for (int r = 0; r < 8; r++) {
        int cl = ty + 8 * r;
        sm[cl][tx] = src[(size_t)cl * HW_ + tx];
    }
    __syncthreads();

    __half2* dst = (__half2*)g_xt;
    const size_t dbase = ((size_t)b * HW_ + s0) * C2_ + (c0 >> 1) + tx;
    #pragma unroll
    for (int r = 0; r < 4; r++) {
        int sl = ty + 8 * r;
        float v0 = sm[2 * tx + 0][sl];
        float v1 = sm[2 * tx + 1][sl];
        dst[dbase + (size_t)sl * C2_] = __floats2half2_rn(v0, v1);
    }
}

// ---------------------------------------------------------------------------
// Gather one batch. blockIdx.x = n*6 + r (oh row r). Warp w handles output
// position (oh=r, ow=w). Lane l accumulates channels 8l..8l+7 via one
// uint4 (8 fp16) per corner -> 512B fully-coalesced warp transactions.
// ---------------------------------------------------------------------------
__global__ void __launch_bounds__(TPB)
gather_kernel(const float* __restrict__ boxes, float* __restrict__ out, int b)
{
    // Let the next transpose launch immediately; then wait for our producer.
    cudaTriggerProgrammaticLaunchCompletion();
    cudaGridDependencySynchronize();

    __shared__ float tile[PPB][C_ + 2];   // row stride 258 floats

    const int blk  = blockIdx.x;
    const int n    = blk / 6;
    const int r    = blk - 6 * n;         // oh row
    const int bn   = b * N_ + n;
    const int tid  = threadIdx.x;
    const int lane = tid & 31;
    const int w    = tid >> 5;            // == ow

    const float* box = boxes + bn * 4;
    const float bx1 = __ldg(box + 0) - 0.5f;
    const float by1 = __ldg(box + 1) - 0.5f;
    const float bx2 = __ldg(box + 2) - 0.5f;
    const float by2 = __ldg(box + 3) - 0.5f;
    const float bw = (bx2 - bx1) * (1.0f / OUT_W);
    const float bh = (by2 - by1) * (1.0f / OUT_H);

    const uint4* xt4 = (const uint4*)g_xt + (size_t)b * HW_ * 32 + lane;

    const int oh = r;
    const int ow = w;

    int   yl[2], yh[2], xl[2], xh[2];
    float wy0[2], wy1[2], wx0[2], wx1[2];
    #pragma unroll
    for (int i = 0; i < 2; i++) {
        float yy = by1 + ((float)oh + ((float)i + 0.5f) * 0.5f) * bh;
        bool  vy = (yy >= -1.0f) && (yy <= (float)H_);
        float cy = fmaxf(yy, 0.0f);
        int   lo = (int)floorf(cy);
        bool  ey = (lo >= H_ - 1);
        yl[i] = ey ? (H_ - 1) : lo;
        yh[i] = ey ? (H_ - 1) : (lo + 1);
        float fy = ey ? 0.0f : (cy - (float)lo);
        wy1[i] = vy ? fy : 0.0f;
        wy0[i] = vy ? (1.0f - fy) : 0.0f;

        float xx = bx1 + ((float)ow + ((float)i + 0.5f) * 0.5f) * bw;
        bool  vx = (xx >= -1.0f) && (xx <= (float)W_);
        float cx = fmaxf(xx, 0.0f);
        int   lx = (int)floorf(cx);
        bool  ex = (lx >= W_ - 1);
        xl[i] = ex ? (W_ - 1) : lx;
        xh[i] = ex ? (W_ - 1) : (lx + 1);
        float fx = ex ? 0.0f : (cx - (float)lx);
        wx1[i] = vx ? fx : 0.0f;
        wx0[i] = vx ? (1.0f - fx) : 0.0f;
    }

    float acc[8];
    #pragma unroll
    for (int k = 0; k < 8; k++) acc[k] = 0.0f;

    #pragma unroll
    for (int iy = 0; iy < 2; iy++) {
        #pragma unroll
        for (int ix = 0; ix < 2; ix++) {
            const int p00 = (yl[iy] * W_ + xl[ix]) * 32;
            const int p01 = (yl[iy] * W_ + xh[ix]) * 32;
            const int p10 = (yh[iy] * W_ + xl[ix]) * 32;
            const int p11 = (yh[iy] * W_ + xh[ix]) * 32;
            const float w00 = wy0[iy] * wx0[ix];
            const float w01 = wy0[iy] * wx1[ix];
            const float w10 = wy1[iy] * wx0[ix];
            const float w11 = wy1[iy] * wx1[ix];

            uint4 v00 = __ldg(xt4 + p00);
            uint4 v01 = __ldg(xt4 + p01);
            uint4 v10 = __ldg(xt4 + p10);
            uint4 v11 = __ldg(xt4 + p11);

            const uint4* vs[4] = { &v00, &v01, &v10, &v11 };
            const float  ws[4] = { w00, w01, w10, w11 };
            #pragma unroll
            for (int c4 = 0; c4 < 4; c4++) {
                const __half2* h = (const __half2*)vs[c4];
                const float wgt = ws[c4];
                #pragma unroll
                for (int j = 0; j < 4; j++) {
                    float2 f = __half22float2(h[j]);
                    acc[2 * j + 0] += wgt * f.x;
                    acc[2 * j + 1] += wgt * f.y;
                }
            }
        }
    }

    float2* row = (float2*)&tile[w][0];
    #pragma unroll
    for (int j = 0; j < 4; j++) {
        row[4 * lane + j] = make_float2(acc[2 * j] * 0.25f,
                                        acc[2 * j + 1] * 0.25f);
    }
    __syncthreads();

    // Output slab: for each channel c, 6 contiguous floats at c*36 + r*6.
    float* obase = out + (size_t)bn * (C_ * NPOS) + r * PPB;
    #pragma unroll
    for (int i = 0; i < (C_ * PPB) / TPB; i++) {   // 8 iterations
        int e = i * TPB + tid;
        int c = e / PPB;
        int p = e - PPB * c;
        obase[c * NPOS + p] = tile[p][c];
    }
}

extern "C" void kernel_launch(void* const* d_in, const int* in_sizes, int n_in,
                              void* d_out, int out_size)
{
    const float* x     = (const float*)d_in[0];
    const float* boxes = (const float*)d_in[1];
    float*       out   = (float*)d_out;

    cudaLaunchAttribute attr;
    attr.id = cudaLaunchAttributeProgrammaticStreamSerialization;
    attr.val.programmaticStreamSerializationAllowed = 1;

    for (int b = 0; b < B_; b++) {
        {   // transpose batch b
            cudaLaunchConfig_t cfg = {};
            cfg.gridDim  = dim3(HW_ / 32, C_ / 64, 1);   // 512 x 4
            cfg.blockDim = dim3(256, 1, 1);
            cfg.stream   = 0;
            cfg.attrs    = (b == 0) ? nullptr : &attr;
            cfg.numAttrs = (b == 0) ? 0 : 1;
            cudaLaunchKernelEx(&cfg, transpose_kernel, x, b);
        }
        {   // gather batch b
            cudaLaunchConfig_t cfg = {};
            cfg.gridDim  = dim3(N_ * 6, 1, 1);           // 384 blocks
            cfg.blockDim = dim3(TPB, 1, 1);
            cfg.stream   = 0;
            cfg.attrs    = &attr;
            cfg.numAttrs = 1;
            cudaLaunchKernelEx(&cfg, gather_kernel, boxes, out, b);
        }
    }
}

// round 8
// speedup vs baseline: 1.0249x; 1.0249x over previous
#include <cuda_runtime.h>
#include <cuda_fp16.h>

// RoIAlign (torchvision aligned=True, sampling_ratio=2) — FUSED pipeline:
// one kernel whose blocks are either transpose-blocks (batch b: x[b] [C,H,W]
// f32 -> g_xt[b] [H,W,C] f16) or gather-blocks (consume g_xt[b]). Gather
// blocks wait on a per-batch ready counter; transpose blocks never wait, so
// dispatch order (T0,G0,T1,G1,...) guarantees forward progress and overlap.

#define B_    8
#define N_    64
#define C_    256
#define C2_   (C_ / 2)
#define H_    128
#define W_    128
#define HW_   (H_ * W_)
#define OUT_H 6
#define OUT_W 6
#define NPOS  36
#define PPB   18             // positions per gather block (half a box)
#define TPB   256

#define CT    2048           // transpose blocks per batch (512 spatial x 4 ch)
#define CG    128            // gather blocks per batch (64 boxes x 2 halves)
#define CHUNK (CT + CG)

// 64 MB scratch + flags (__device__ globals: allowed)
__device__ __half g_xt[(size_t)B_ * HW_ * C_];
__device__ int    g_ready[B_];   // zero-init; self-cleaned each launch
__device__ int    g_gdone[B_];

__global__ void __launch_bounds__(TPB)
fused_kernel(const float* __restrict__ x,
             const float* __restrict__ boxes,
             float* __restrict__ out)
{
    __shared__ float sbuf[PPB * 258];    // max(T: 64*33, G: 18*258) floats

    const int b   = blockIdx.x / CHUNK;
    const int r   = blockIdx.x - b * CHUNK;
    const int tid = threadIdx.x;

    if (r < CT) {
        // ------------------- transpose role -------------------
        float (*sm)[33] = (float (*)[33])sbuf;
        const int s0 = (r & 511) * 32;
        const int c0 = (r >> 9) * 64;
        const int tx = tid & 31;
        const int ty = tid >> 5;

        const float* src = x + ((size_t)b * C_ + c0) * HW_ + s0;
        #pragma unroll
        for (int i = 0; i < 8; i++) {
            int cl = ty + 8 * i;
            sm[cl][tx] = src[(size_t)cl * HW_ + tx];
        }
        __syncthreads();

        __half2* dst = (__half2*)g_xt;
        const size_t dbase = ((size_t)b * HW_ + s0) * C2_ + (c0 >> 1) + tx;
        #pragma unroll
        for (int i = 0; i < 4; i++) {
            int sl = ty + 8 * i;
            float v0 = sm[2 * tx + 0][sl];
            float v1 = sm[2 * tx + 1][sl];
            dst[dbase + (size_t)sl * C2_] = __floats2half2_rn(v0, v1);
        }
        __syncthreads();
        if (tid == 0) {
            __threadfence();                 // release g_xt writes
            atomicAdd(&g_ready[b], 1);
        }
        return;
    }

    // ------------------- gather role -------------------
    const int g    = r - CT;
    const int bn   = b * N_ + (g >> 1);
    const int half = g & 1;                  // oh rows 0-2 or 3-5
    const int lane = tid & 31;
    const int w    = tid >> 5;

    // Wait until all transpose blocks for batch b are done.
    if (tid == 0) {
        while (atomicAdd(&g_ready[b], 0) < CT) __nanosleep(256);
        __threadfence();                     // acquire
    }
    __syncthreads();

    float (*tile)[258] = (float (*)[258])sbuf;

    const float* box = boxes + bn * 4;
    const float bx1 = __ldg(box + 0) - 0.5f;
    const float by1 = __ldg(box + 1) - 0.5f;
    const float bx2 = __ldg(box + 2) - 0.5f;
    const float by2 = __ldg(box + 3) - 0.5f;
    const float bw = (bx2 - bx1) * (1.0f / OUT_W);
    const float bh = (by2 - by1) * (1.0f / OUT_H);

    const uint4* xt4 = (const uint4*)g_xt + (size_t)(bn >> 6) * HW_ * 32 + lane;

    for (int pos = w; pos < PPB; pos += 8) {
        const int gpos = half * PPB + pos;
        const int oh = gpos / 6;
        const int ow = gpos - 6 * oh;

        int   yl[2], yh[2], xl[2], xh[2];
        float wy0[2], wy1[2], wx0[2], wx1[2];
        #pragma unroll
        for (int i = 0; i < 2; i++) {
            float yy = by1 + ((float)oh + ((float)i + 0.5f) * 0.5f) * bh;
            bool  vy = (yy >= -1.0f) && (yy <= (float)H_);
            float cy = fmaxf(yy, 0.0f);
            int   lo = (int)floorf(cy);
            bool  ey = (lo >= H_ - 1);
            yl[i] = ey ? (H_ - 1) : lo;
            yh[i] = ey ? (H_ - 1) : (lo + 1);
            float fy = ey ? 0.0f : (cy - (float)lo);
            wy1[i] = vy ? fy : 0.0f;
            wy0[i] = vy ? (1.0f - fy) : 0.0f;

            float xx = bx1 + ((float)ow + ((float)i + 0.5f) * 0.5f) * bw;
            bool  vx = (xx >= -1.0f) && (xx <= (float)W_);
            float cx = fmaxf(xx, 0.0f);
            int   lx = (int)floorf(cx);
            bool  ex = (lx >= W_ - 1);
            xl[i] = ex ? (W_ - 1) : lx;
            xh[i] = ex ? (W_ - 1) : (lx + 1);
            float fx = ex ? 0.0f : (cx - (float)lx);
            wx1[i] = vx ? fx : 0.0f;
            wx0[i] = vx ? (1.0f - fx) : 0.0f;
        }

        float acc[8];
        #pragma unroll
        for (int k = 0; k < 8; k++) acc[k] = 0.0f;

        #pragma unroll
        for (int iy = 0; iy < 2; iy++) {
            #pragma unroll
            for (int ix = 0; ix < 2; ix++) {
                const int p00 = (yl[iy] * W_ + xl[ix]) * 32;
                const int p01 = (yl[iy] * W_ + xh[ix]) * 32;
                const int p10 = (yh[iy] * W_ + xl[ix]) * 32;
                const int p11 = (yh[iy] * W_ + xh[ix]) * 32;
                const float w00 = wy0[iy] * wx0[ix];
                const float w01 = wy0[iy] * wx1[ix];
                const float w10 = wy1[iy] * wx0[ix];
                const float w11 = wy1[iy] * wx1[ix];

                uint4 v00 = __ldg(xt4 + p00);
                uint4 v01 = __ldg(xt4 + p01);
                uint4 v10 = __ldg(xt4 + p10);
                uint4 v11 = __ldg(xt4 + p11);

                const uint4* vs[4] = { &v00, &v01, &v10, &v11 };
                const float  ws[4] = { w00, w01, w10, w11 };
                #pragma unroll
                for (int c4 = 0; c4 < 4; c4++) {
                    const __half2* h = (const __half2*)vs[c4];
                    const float wgt = ws[c4];
                    #pragma unroll
                    for (int j = 0; j < 4; j++) {
                        float2 f = __half22float2(h[j]);
                        acc[2 * j + 0] += wgt * f.x;
                        acc[2 * j + 1] += wgt * f.y;
                    }
                }
            }
        }

        float2* row = (float2*)&tile[pos][0];     // stride 258 -> 8B aligned
        #pragma unroll
        for (int j = 0; j < 4; j++) {
            row[4 * lane + j] = make_float2(acc[2 * j] * 0.25f,
                                            acc[2 * j + 1] * 0.25f);
        }
    }
    __syncthreads();

    // Output slab: for each channel c, 18 contiguous floats at c*36 + half*18.
    float* obase = out + (size_t)bn * (C_ * NPOS) + half * PPB;
    #pragma unroll
    for (int i = 0; i < (C_ * PPB) / TPB; i++) {   // 18 iterations
        int e = i * TPB + tid;
        int c = e / PPB;
        int p = e - PPB * c;
        obase[c * NPOS + p] = tile[p][c];
    }

    // Self-clean flags so the next graph replay starts from zero.
    __syncthreads();
    if (tid == 0) {
        if (atomicAdd(&g_gdone[b], 1) == CG - 1) {
            atomicExch(&g_ready[b], 0);
            atomicExch(&g_gdone[b], 0);
        }
    }
}

extern "C" void kernel_launch(void* const* d_in, const int* in_sizes, int n_in,
                              void* d_out, int out_size)
{
    const float* x     = (const float*)d_in[0];
    const float* boxes = (const float*)d_in[1];
    float*       out   = (float*)d_out;

    fused_kernel<<<B_ * CHUNK, TPB>>>(x, boxes, out);
}

// round 9
// speedup vs baseline: 1.4431x; 1.4080x over previous
#include <cuda_runtime.h>
#include <cuda_fp16.h>

// RoIAlign (torchvision aligned=True, sampling_ratio=2) — two-pass, two-stage,
// two-stream overlap:
//   stage S0: T(b0..3); stage S1: T(b4..7) runs CONCURRENT with G(b0..3) on a
//   forked stream; then G(b4..7). Kernels identical to the proven R6 configs;
//   overlap comes purely from graph topology (event fork/join during capture).

#define B_    8
#define N_    64
#define C_    256
#define C2_   (C_ / 2)
#define H_    128
#define W_    128
#define HW_   (H_ * W_)
#define OUT_H 6
#define OUT_W 6
#define NPOS  36
#define PPB   18             // positions per gather block (half a box)
#define GTPB  192            // gather threads (6 warps)

// 8 * 16384 * 256 halves = 64 MB scratch (__device__ global: allowed)
__device__ __half g_xt[(size_t)B_ * HW_ * C_];

// ---------------------------------------------------------------------------
// Transpose batches [b0, b0+nb): [C, HW] f32 -> [HW, C] f16.
// ---------------------------------------------------------------------------
__global__ void __launch_bounds__(256)
transpose_kernel(const float* __restrict__ x, int b0)
{
    __shared__ float sm[64][33];

    const int b  = b0 + blockIdx.z;
    const int c0 = blockIdx.y * 64;
    const int s0 = blockIdx.x * 32;
    const int tid = threadIdx.x;
    const int tx = tid & 31;
    const int ty = tid >> 5;

    const float* src = x + ((size_t)b * C_ + c0) * HW_ + s0;
    #pragma unroll
    for (int r = 0; r < 8; r++) {
        int cl = ty + 8 * r;
        sm[cl][tx] = src[(size_t)cl * HW_ + tx];
    }
    __syncthreads();

    __half2* dst = (__half2*)g_xt;
    const size_t dbase = ((size_t)b * HW_ + s0) * C2_ + (c0 >> 1) + tx;
    #pragma unroll
    for (int r = 0; r < 4; r++) {
        int sl = ty + 8 * r;
        float v0 = sm[2 * tx + 0][sl];
        float v1 = sm[2 * tx + 1][sl];
        dst[dbase + (size_t)sl * C2_] = __floats2half2_rn(v0, v1);
    }
}

// ---------------------------------------------------------------------------
// Gather batches [b0, b0+nb). blockIdx.x = local bn*2 + half. 6 warps; warp w
// handles positions w, w+6, w+12 of its 18-position half. Lane l covers
// channels 8l..8l+7 via one uint4 (8 fp16) per corner -> 512B coalesced.
// ---------------------------------------------------------------------------
__global__ void __launch_bounds__(GTPB)
gather_kernel(const float* __restrict__ boxes, float* __restrict__ out, int b0)
{
    __shared__ float tile[PPB][C_ + 2];   // row stride 258 floats

    const int blk  = blockIdx.x;
    const int bn   = b0 * N_ + (blk >> 1);
    const int half = blk & 1;             // oh rows 0-2 or 3-5
    const int b    = bn >> 6;
    const int tid  = threadIdx.x;
    const int lane = tid & 31;
    const int w    = tid >> 5;

    const float* box = boxes + bn * 4;
    const float bx1 = __ldg(box + 0) - 0.5f;
    const float by1 = __ldg(box + 1) - 0.5f;
    const float bx2 = __ldg(box + 2) - 0.5f;
    const float by2 = __ldg(box + 3) - 0.5f;
    const float bw = (bx2 - bx1) * (1.0f / OUT_W);
    const float bh = (by2 - by1) * (1.0f / OUT_H);

    const uint4* xt4 = (const uint4*)g_xt + (size_t)b * HW_ * 32 + lane;

    #pragma unroll
    for (int pl = 0; pl < 3; pl++) {
        const int pos  = w + 6 * pl;               // 0..17 local
        const int gpos = half * PPB + pos;         // 0..35 global
        const int oh = gpos / 6;
        const int ow = gpos - 6 * oh;

        int   yl[2], yh[2], xl[2], xh[2];
        float wy0[2], wy1[2], wx0[2], wx1[2];
        #pragma unroll
        for (int i = 0; i < 2; i++) {
            float yy = by1 + ((float)oh + ((float)i + 0.5f) * 0.5f) * bh;
            bool  vy = (yy >= -1.0f) && (yy <= (float)H_);
            float cy = fmaxf(yy, 0.0f);
            int   lo = (int)floorf(cy);
            bool  ey = (lo >= H_ - 1);
            yl[i] = ey ? (H_ - 1) : lo;
            yh[i] = ey ? (H_ - 1) : (lo + 1);
            float fy = ey ? 0.0f : (cy - (float)lo);
            wy1[i] = vy ? fy : 0.0f;
            wy0[i] = vy ? (1.0f - fy) : 0.0f;

            float xx = bx1 + ((float)ow + ((float)i + 0.5f) * 0.5f) * bw;
            bool  vx = (xx >= -1.0f) && (xx <= (float)W_);
            float cx = fmaxf(xx, 0.0f);
            int   lx = (int)floorf(cx);
            bool  ex = (lx >= W_ - 1);
            xl[i] = ex ? (W_ - 1) : lx;
            xh[i] = ex ? (W_ - 1) : (lx + 1);
            float fx = ex ? 0.0f : (cx - (float)lx);
            wx1[i] = vx ? fx : 0.0f;
            wx0[i] = vx ? (1.0f - fx) : 0.0f;
        }

        float acc[8];
        #pragma unroll
        for (int k = 0; k < 8; k++) acc[k] = 0.0f;

        #pragma unroll
        for (int iy = 0; iy < 2; iy++) {
            #pragma unroll
            for (int ix = 0; ix < 2; ix++) {
                const int p00 = (yl[iy] * W_ + xl[ix]) * 32;
                const int p01 = (yl[iy] * W_ + xh[ix]) * 32;
                const int p10 = (yh[iy] * W_ + xl[ix]) * 32;
                const int p11 = (yh[iy] * W_ + xh[ix]) * 32;
                const float w00 = wy0[iy] * wx0[ix];
                const float w01 = wy0[iy] * wx1[ix];
                const float w10 = wy1[iy] * wx0[ix];
                const float w11 = wy1[iy] * wx1[ix];

                uint4 v00 = __ldg(xt4 + p00);
                uint4 v01 = __ldg(xt4 + p01);
                uint4 v10 = __ldg(xt4 + p10);
                uint4 v11 = __ldg(xt4 + p11);

                const uint4* vs[4] = { &v00, &v01, &v10, &v11 };
                const float  ws[4] = { w00, w01, w10, w11 };
                #pragma unroll
                for (int c4 = 0; c4 < 4; c4++) {
                    const __half2* h = (const __half2*)vs[c4];
                    const float wgt = ws[c4];
                    #pragma unroll
                    for (int j = 0; j < 4; j++) {
                        float2 f = __half22float2(h[j]);
                        acc[2 * j + 0] += wgt * f.x;
                        acc[2 * j + 1] += wgt * f.y;
                    }
                }
            }
        }

        float2* row = (float2*)&tile[pos][0];
        #pragma unroll
        for (int j = 0; j < 4; j++) {
            row[4 * lane + j] = make_float2(acc[2 * j] * 0.25f,
                                            acc[2 * j + 1] * 0.25f);
        }
    }
    __syncthreads();

    // Output slab: for each channel c, 18 contiguous floats at c*36 + half*18.
    float* obase = out + (size_t)bn * (C_ * NPOS) + half * PPB;
    #pragma unroll
    for (int i = 0; i < (C_ * PPB) / GTPB; i++) {   // 24 iterations
        int e = i * GTPB + tid;
        int c = e / PPB;
        int p = e - PPB * c;
        obase[c * NPOS + p] = tile[p][c];
    }
}

extern "C" void kernel_launch(void* const* d_in, const int* in_sizes, int n_in,
                              void* d_out, int out_size)
{
    const float* x     = (const float*)d_in[0];
    const float* boxes = (const float*)d_in[1];
    float*       out   = (float*)d_out;

    // Fork a side stream during capture (record/wait become graph edges).
    cudaStream_t s2;
    cudaStreamCreateWithFlags(&s2, cudaStreamNonBlocking);
    cudaEvent_t e0, e1, eJ;
    cudaEventCreateWithFlags(&e0, cudaEventDisableTiming);
    cudaEventCreateWithFlags(&e1, cudaEventDisableTiming);
    cudaEventCreateWithFlags(&eJ, cudaEventDisableTiming);

    dim3 tgrid(HW_ / 32, C_ / 64, B_ / 2);   // 512 x 4 x 4 per stage

    // main stream: T(0..3), T(4..7)
    transpose_kernel<<<tgrid, 256, 0, 0>>>(x, 0);
    cudaEventRecord(e0, 0);
    transpose_kernel<<<tgrid, 256, 0, 0>>>(x, 4);
    cudaEventRecord(e1, 0);

    // side stream: G(0..3) overlaps T(4..7); then G(4..7)
    cudaStreamWaitEvent(s2, e0, 0);
    gather_kernel<<<(B_ / 2) * N_ * 2, GTPB, 0, s2>>>(boxes, out, 0);
    cudaStreamWaitEvent(s2, e1, 0);
    gather_kernel<<<(B_ / 2) * N_ * 2, GTPB, 0, s2>>>(boxes, out, 4);
    cudaEventRecord(eJ, s2);

    // join back to the captured origin stream
    cudaStreamWaitEvent(0, eJ, 0);
}